// round 16
// baseline (speedup 1.0000x reference)
#include <cuda_runtime.h>

// ---------------------------------------------------------------------------
// CubeAttention v13. N=20, D=64, CAP=32, SCOPE=2, WIDTH=5, P=125.
//   Q  = SE@Wq+bq ; K = SE@Wk[96:]      (zero-padded 22^3 cube)
//   W2 = Wv[96:]@Wo ; V' = SE@W2        (value rows pre-multiplied by Wo)
//   krel[p] = relpos@Wk[:96]+bk ; vrel'[p] = (relpos@Wv[:96]+bv)@Wo
//   logits[v][p] = Q[v].krel[p] + Q[v].K[gather]  (zero pad rows => rel only)
//   out[v] = sum_p sc[p]*(V'[gather] + vrel'[p]) + bo
// mask quirk: validity at (x+a,y+b,z+c) strict [1,19]; gather at (x+b,y+a,z+c)
// v13: v10 + phase-3 reads sc directly for vrel2 weights (wt shrinks to
//      [216][8]) -> smem 44.2KB -> 5 CTAs/SM. rel_w2 grid raised to 157.
// ---------------------------------------------------------------------------

#define NV 8000
#define NP 125
#define PD 22
#define PR (PD * PD * PD)
// smem float offsets (attn):
#define SM_VST 0                    // float4[108][17] = 7344 floats
#define SM_SC  7344                 // [8][128]  = 1024
#define SM_QT  8368                 // [64][8]   = 512
#define SM_WT  8880                 // [216][8] = 1728 ; also phase-1 scratch
#define SM_LG  10608                // int lutg[216]
#define SM_LP  10824                // int lutp[216]
#define SMF    11040                // 44160 B -> 5 CTAs/SM

#define FMA4(A, s, V) \
    A.x = fmaf(s, V.x, A.x); A.y = fmaf(s, V.y, A.y); \
    A.z = fmaf(s, V.z, A.z); A.w = fmaf(s, V.w, A.w)

__device__ float g_Q[NV * 64];
__device__ float g_K[PR * 64];      // zero-padded
__device__ float g_V[PR * 64];      // V' (pre-Wo), zero-padded
__device__ float g_W2[64 * 64];
__device__ float g_krelT[64 * NP];
__device__ float g_vrel2[NP * 64];  // (relpos@Wv_rel + bv) @ Wo

// ---------------------------------------------------------------------------
// K1: rel tables + vrel2 (blocks 0..124) ; W2 (blocks 125..156, 128 out each)
// ---------------------------------------------------------------------------
__global__ void __launch_bounds__(256) rel_w2_kernel(
    const float* __restrict__ rw,
    const float* __restrict__ Wk, const float* __restrict__ bk,
    const float* __restrict__ Wv, const float* __restrict__ bv,
    const float* __restrict__ Wo)
{
    int blk = blockIdx.x;
    int tid = threadIdx.x;
    if (blk >= NP) {                       // W2: 32 blocks x 128 outputs
        if (tid < 128) {
            int idx = (blk - NP) * 128 + tid;
            int i = idx >> 6, ch = idx & 63;
            float acc = 0.0f;
            #pragma unroll 16
            for (int k = 0; k < 64; k++)
                acc = fmaf(Wv[(96 + i) * 64 + k], Wo[k * 64 + ch], acc);
            g_W2[idx] = acc;
        }
        return;
    }
    __shared__ float pk[3][64], pv[3][64], vsm[64], v2p[2][64];
    int p = blk;
    int ch = tid & 63;
    int part = tid >> 6;
    int a = p / 25, b = (p / 5) % 5, c = p % 5;

    if (part < 3) {
        int digit = (part == 0) ? a : (part == 1) ? b : c;
        const float* rwd = rw + digit * 32;
        const float* Wkp = Wk + part * 32 * 64 + ch;
        const float* Wvp = Wv + part * 32 * 64 + ch;
        float kk = 0.0f, vv = 0.0f;
        #pragma unroll 8
        for (int j = 0; j < 32; j++) {
            float rv = rwd[j];
            kk = fmaf(rv, Wkp[j * 64], kk);
            vv = fmaf(rv, Wvp[j * 64], vv);
        }
        pk[part][ch] = kk;
        pv[part][ch] = vv;
    }
    __syncthreads();
    if (part == 0) {
        g_krelT[ch * NP + p] = bk[ch] + (pk[0][ch] + pk[1][ch]) + pk[2][ch];
        vsm[ch]              = bv[ch] + (pv[0][ch] + pv[1][ch]) + pv[2][ch];
    }
    __syncthreads();
    if (part < 2) {
        const float* Wop = Wo + part * 32 * 64 + ch;
        const float* vp  = vsm + part * 32;
        float acc = 0.0f;
        #pragma unroll 8
        for (int k = 0; k < 32; k++)
            acc = fmaf(vp[k], Wop[k * 64], acc);
        v2p[part][ch] = acc;
    }
    __syncthreads();
    if (part == 0)
        g_vrel2[p * 64 + ch] = v2p[0][ch] + v2p[1][ch];
}

// ---------------------------------------------------------------------------
// K2: prep blocked GEMM. sel 0: Q=SE@Wq+bq ; 1: K=SE@Wk[96:] ; 2: V'=SE@W2
// ---------------------------------------------------------------------------
__global__ void __launch_bounds__(256) prep_kernel(
    const float* __restrict__ se,
    const float* __restrict__ Wq, const float* __restrict__ bq,
    const float* __restrict__ Wk)
{
    __shared__ float Wsm[64 * 64];
    __shared__ float ssm[32 * 64];
    int sel = blockIdx.y;
    int tid = threadIdx.x;
    const float* W = (sel == 0) ? Wq : (sel == 1) ? (Wk + 96 * 64) : g_W2;

    #pragma unroll
    for (int i = tid; i < 1024; i += 256)
        ((float4*)Wsm)[i] = ((const float4*)W)[i];
    int base = blockIdx.x * 32;
    #pragma unroll
    for (int i = tid; i < 512; i += 256)
        ((float4*)ssm)[i] = ((const float4*)(se + base * 64))[i];
    __syncthreads();

    int c  = tid & 63;
    int r0 = (tid >> 6) * 8;
    float acc[8];
    float bias = (sel == 0) ? bq[c] : 0.0f;
    #pragma unroll
    for (int j = 0; j < 8; j++) acc[j] = bias;

    #pragma unroll 4
    for (int k = 0; k < 64; k++) {
        float wv = Wsm[k * 64 + c];
        #pragma unroll
        for (int j = 0; j < 8; j++)
            acc[j] = fmaf(ssm[(r0 + j) * 64 + k], wv, acc[j]);
    }
    #pragma unroll
    for (int j = 0; j < 8; j++) {
        int v = base + r0 + j;
        if (sel == 0) {
            g_Q[v * 64 + c] = acc[j];
        } else {
            int x = v / 400, y = (v / 20) % 20, z = v % 20;
            int pi = ((x + 2) * PD + (y + 2)) * PD + (z + 2);
            ((sel == 1) ? g_K : g_V)[pi * 64 + c] = acc[j];
        }
    }
}

// ---------------------------------------------------------------------------
// K3: attention. 2x2x2 voxels / block, 256 threads, 5 CTAs/SM.
// ---------------------------------------------------------------------------
__global__ void __launch_bounds__(256, 5) attn_kernel(
    const float* __restrict__ bo, float* __restrict__ out)
{
    extern __shared__ float sm[];
    float4* vst4 = (float4*)(sm + SM_VST);       // [108 rows][17]
    float*  sc   = sm + SM_SC;
    float*  qt   = sm + SM_QT;
    float*  wt   = sm + SM_WT;                   // phase-1 scratch, then wt
    int*    lutg = (int*)(sm + SM_LG);
    int*    lutp = (int*)(sm + SM_LP);

    int tid = threadIdx.x;
    int bz = blockIdx.x % 10, by = (blockIdx.x / 10) % 10, bx = blockIdx.x / 100;
    int X = bx * 2, Y = by * 2, Z = bz * 2;
    int prow = (X * PD + Y) * PD + Z;

    // ---- LUT build ----
    if (tid < 216) {
        int r = tid;
        int rx = r / 36, rem = r - rx * 36, ry = rem / 6, rz = rem - ry * 6;
        lutg[r] = (prow + (rx * PD + ry) * PD + rz) * 16;
        lutp[r] = rx | (ry << 8) | (rz << 16);
    }
    __syncthreads();

    // ---- stage K rows 0..107 + qt ----
    const float4* K4 = (const float4*)g_K;
    #pragma unroll
    for (int i = tid; i < 108 * 16; i += 256)
        vst4[(i >> 4) * 17 + (i & 15)] = K4[lutg[i >> 4] + (i & 15)];
    #pragma unroll
    for (int i = tid; i < 512; i += 256) {
        int v = i >> 6, k = i & 63;
        int gv = ((X + (v >> 2)) * 20 + Y + ((v >> 1) & 1)) * 20 + Z + (v & 1);
        qt[k * 8 + v] = g_Q[gv * 64 + k];
    }
    __syncthreads();

    // ---- QR phase: sc[v][p] = Q[v].krel[p]  (250 threads, 4 voxels each) ----
    if (tid < 250) {
        int half = tid / 125;
        int p = tid - half * 125;
        float4 a = make_float4(0.f, 0.f, 0.f, 0.f);
        const float* kp = g_krelT + p;
        #pragma unroll 8
        for (int k = 0; k < 64; k++) {
            float kr = kp[k * NP];
            float4 qv = *(const float4*)(qt + k * 8 + half * 4);
            FMA4(a, kr, qv);
        }
        sc[(half * 4 + 0) * 128 + p] = a.x;
        sc[(half * 4 + 1) * 128 + p] = a.y;
        sc[(half * 4 + 2) * 128 + p] = a.z;
        sc[(half * 4 + 3) * 128 + p] = a.w;
    }
    __syncthreads();

    // ---- phase 1: rowdot (k-split, 216 threads) + masked scatter ----
    #pragma unroll
    for (int pass = 0; pass < 2; pass++) {
        if (pass == 1) {
            __syncthreads();         // pass-0 reads of vst4 done
            #pragma unroll
            for (int i = tid; i < 108 * 16; i += 256)
                vst4[(i >> 4) * 17 + (i & 15)] = K4[lutg[108 + (i >> 4)] + (i & 15)];
            __syncthreads();
        }
        float acc[8];
        int rl = 0;
        if (tid < 216) {
            int h = tid >= 108;      // k4-half
            rl = tid - h * 108;      // local row
            #pragma unroll
            for (int j = 0; j < 8; j++) acc[j] = 0.0f;
            int k4A = h * 8;
            #pragma unroll
            for (int k4 = k4A; k4 < k4A + 8; k4++) {
                float4 kv = vst4[rl * 17 + k4];
                const float* qb = qt + k4 * 32;
                #pragma unroll
                for (int kk = 0; kk < 4; kk++) {
                    float kf = (kk == 0) ? kv.x : (kk == 1) ? kv.y
                             : (kk == 2) ? kv.z : kv.w;
                    float4 qa = *(const float4*)(qb + kk * 8);
                    float4 qc = *(const float4*)(qb + kk * 8 + 4);
                    acc[0] = fmaf(kf, qa.x, acc[0]); acc[1] = fmaf(kf, qa.y, acc[1]);
                    acc[2] = fmaf(kf, qa.z, acc[2]); acc[3] = fmaf(kf, qa.w, acc[3]);
                    acc[4] = fmaf(kf, qc.x, acc[4]); acc[5] = fmaf(kf, qc.y, acc[5]);
                    acc[6] = fmaf(kf, qc.z, acc[6]); acc[7] = fmaf(kf, qc.w, acc[7]);
                }
            }
            if (tid >= 108) {        // h=1 partials -> scratch (stride 9)
                #pragma unroll
                for (int j = 0; j < 8; j++) wt[rl * 9 + j] = acc[j];
            }
        }
        __syncthreads();
        if (tid < 108) {
            int r = pass * 108 + tid;
            #pragma unroll
            for (int j = 0; j < 8; j++) acc[j] += wt[rl * 9 + j];
            int pk = lutp[r];
            int rx = pk & 255, ry = (pk >> 8) & 255, rz = pk >> 16;
            #pragma unroll
            for (int v = 0; v < 8; v++) {
                int lx = v >> 2, ly = (v >> 1) & 1, lz = v & 1;
                int a = ry - ly, b = rx - lx, c = rz - lz;
                if (((unsigned)a < 5u) & ((unsigned)b < 5u) & ((unsigned)c < 5u)) {
                    int p = (a * 5 + b) * 5 + c;
                    int mx = X + lx + a - 2, my = Y + ly + b - 2, mz = Z + lz + c - 2;
                    bool mv = (mx >= 1) & (mx <= 19) & (my >= 1) & (my <= 19)
                            & (mz >= 1) & (mz <= 19);
                    sc[v * 128 + p] = mv ? (sc[v * 128 + p] + acc[v]) : -1e9f;
                }
            }
        }
    }
    __syncthreads();

    // ---- phase 2: per-voxel softmax (warp = voxel); masked -> exact 0 ----
    {
        int w = tid >> 5, lane = tid & 31;
        float l0 = sc[w * 128 + lane];
        float l1 = sc[w * 128 + lane + 32];
        float l2 = sc[w * 128 + lane + 64];
        float l3 = (lane < 29) ? sc[w * 128 + lane + 96] : -1e30f;
        float m = fmaxf(fmaxf(l0, l1), fmaxf(l2, l3));
        #pragma unroll
        for (int o = 16; o; o >>= 1)
            m = fmaxf(m, __shfl_xor_sync(0xffffffffu, m, o));
        float e0 = __expf(l0 - m), e1 = __expf(l1 - m);
        float e2 = __expf(l2 - m), e3 = __expf(l3 - m);
        float s = (e0 + e1) + (e2 + e3);
        #pragma unroll
        for (int o = 16; o; o >>= 1)
            s += __shfl_xor_sync(0xffffffffu, s, o);
        float inv = 1.0f / s;
        sc[w * 128 + lane]      = e0 * inv;
        sc[w * 128 + lane + 32] = e1 * inv;
        sc[w * 128 + lane + 64] = e2 * inv;
        if (lane < 29) sc[w * 128 + lane + 96] = e3 * inv;
    }
    __syncthreads();

    // ---- stage V' rows 0..107 + build wt[216][8] (region rows only) ----
    const float4* V4 = (const float4*)g_V;
    #pragma unroll
    for (int i = tid; i < 108 * 16; i += 256)
        vst4[(i >> 4) * 17 + (i & 15)] = V4[lutg[i >> 4] + (i & 15)];
    for (int i = tid; i < 216 * 8; i += 256) {
        int r = i >> 3, v = i & 7;
        int pk = lutp[r];
        int rx = pk & 255, ry = (pk >> 8) & 255, rz = pk >> 16;
        int lx = v >> 2, ly = (v >> 1) & 1, lz = v & 1;
        int a = ry - ly, b = rx - lx, c = rz - lz;
        wt[i] = (((unsigned)a < 5u) & ((unsigned)b < 5u) & ((unsigned)c < 5u))
                ? sc[v * 128 + (a * 5 + b) * 5 + c] : 0.0f;
    }
    __syncthreads();

    // ---- phase 3: value GEMM, float4 register tile, 2 passes ----
    int rg = tid >> 4, c4 = tid & 15;
    float4 a[8];
    #pragma unroll
    for (int j = 0; j < 8; j++) a[j] = make_float4(0.f, 0.f, 0.f, 0.f);

    {   // pass A: region rows 0..107 (wt rows 0..107)
        int rA = (rg * 108) >> 4;
        int rE = ((rg + 1) * 108) >> 4;
        #pragma unroll 2
        for (int r = rA; r < rE; r++) {
            float4 v4 = vst4[r * 17 + c4];
            float4 w0 = *(const float4*)(wt + r * 8);
            float4 w1 = *(const float4*)(wt + r * 8 + 4);
            FMA4(a[0], w0.x, v4); FMA4(a[1], w0.y, v4);
            FMA4(a[2], w0.z, v4); FMA4(a[3], w0.w, v4);
            FMA4(a[4], w1.x, v4); FMA4(a[5], w1.y, v4);
            FMA4(a[6], w1.z, v4); FMA4(a[7], w1.w, v4);
        }
    }
    __syncthreads();
    #pragma unroll
    for (int i = tid; i < 108 * 16; i += 256)
        vst4[(i >> 4) * 17 + (i & 15)] = V4[lutg[108 + (i >> 4)] + (i & 15)];
    __syncthreads();
    {   // pass B: region rows 108..215 (wt rows 108..215) + vrel2 rows (sc)
        const float4* VR4 = (const float4*)g_vrel2;
        int rA = (rg * 233) >> 4;
        int rE = ((rg + 1) * 233) >> 4;
        #pragma unroll 2
        for (int r = rA; r < rE; r++) {
            if (r < 108) {
                float4 v4 = vst4[r * 17 + c4];
                const float* wr = wt + (108 + r) * 8;
                float4 w0 = *(const float4*)(wr);
                float4 w1 = *(const float4*)(wr + 4);
                FMA4(a[0], w0.x, v4); FMA4(a[1], w0.y, v4);
                FMA4(a[2], w0.z, v4); FMA4(a[3], w0.w, v4);
                FMA4(a[4], w1.x, v4); FMA4(a[5], w1.y, v4);
                FMA4(a[6], w1.z, v4); FMA4(a[7], w1.w, v4);
            } else {
                int p = r - 108;
                float4 v4 = VR4[p * 16 + c4];
                FMA4(a[0], sc[0 * 128 + p], v4);
                FMA4(a[1], sc[1 * 128 + p], v4);
                FMA4(a[2], sc[2 * 128 + p], v4);
                FMA4(a[3], sc[3 * 128 + p], v4);
                FMA4(a[4], sc[4 * 128 + p], v4);
                FMA4(a[5], sc[5 * 128 + p], v4);
                FMA4(a[6], sc[6 * 128 + p], v4);
                FMA4(a[7], sc[7 * 128 + p], v4);
            }
        }
    }
    __syncthreads();                 // vst4/sc/qt dead; reuse as partials
    float4* pts4 = (float4*)sm;      // [16 rg][8 v][16 c4]
    #pragma unroll
    for (int j = 0; j < 8; j++) pts4[rg * 128 + j * 16 + c4] = a[j];
    __syncthreads();

    // ---- reduce partials + bo, STG.128 ----
    if (tid < 128) {
        int v = tid >> 4, cc4 = tid & 15;
        float4 s = pts4[v * 16 + cc4];
        #pragma unroll
        for (int r2 = 1; r2 < 16; r2++) {
            float4 t = pts4[r2 * 128 + v * 16 + cc4];
            s.x += t.x; s.y += t.y; s.z += t.z; s.w += t.w;
        }
        float4 b4 = ((const float4*)bo)[cc4];
        s.x += b4.x; s.y += b4.y; s.z += b4.z; s.w += b4.w;
        int gv = ((X + (v >> 2)) * 20 + Y + ((v >> 1) & 1)) * 20 + Z + (v & 1);
        ((float4*)out)[gv * 16 + cc4] = s;
    }
}

// ---------------------------------------------------------------------------
// Launch
// d_in: 0=spatial_embeddings 1=relpos_w 2=Wq 3=bq 4=Wk 5=bk 6=Wv 7=bv 8=Wo 9=bo
// ---------------------------------------------------------------------------
extern "C" void kernel_launch(void* const* d_in, const int* in_sizes, int n_in,
                              void* d_out, int out_size)
{
    const float* se = (const float*)d_in[0];
    const float* rw = (const float*)d_in[1];
    const float* Wq = (const float*)d_in[2];
    const float* bq = (const float*)d_in[3];
    const float* Wk = (const float*)d_in[4];
    const float* bk = (const float*)d_in[5];
    const float* Wv = (const float*)d_in[6];
    const float* bv = (const float*)d_in[7];
    const float* Wo = (const float*)d_in[8];
    const float* bo = (const float*)d_in[9];
    float* out = (float*)d_out;

    cudaFuncSetAttribute(attn_kernel, cudaFuncAttributeMaxDynamicSharedMemorySize,
                         SMF * 4);

    rel_w2_kernel<<<NP + 32, 256>>>(rw, Wk, bk, Wv, bv, Wo);
    prep_kernel<<<dim3(250, 3), 256>>>(se, Wq, bq, Wk);
    attn_kernel<<<1000, 256, SMF * 4>>>(bo, out);
}

// round 17
// speedup vs baseline: 1.1289x; 1.1289x over previous
#include <cuda_runtime.h>

// ---------------------------------------------------------------------------
// CubeAttention v14. N=20, D=64, CAP=32, SCOPE=2, WIDTH=5, P=125.
//   Q  = SE@Wq+bq ; K = SE@Wk[96:]      (zero-padded 22^3 cube)
//   W2 = Wv[96:]@Wo ; V' = SE@W2        (value rows pre-multiplied by Wo)
//   krel[p] = relpos@Wk[:96]+bk ; vrel'[p] = (relpos@Wv[:96]+bv)@Wo
//   logits[v][p] = Q[v].krel[p] + Q[v].K[gather]  (zero pad rows => rel only)
//   out[v] = sum_p sc[p]*(V'[gather] + vrel'[p]) + bo
// mask quirk: validity at (x+a,y+b,z+c) strict [1,19]; gather at (x+b,y+a,z+c)
// v14: v10 math, restructured attn segments with register-prefetch staging
//      (K1 under QR, K2 under pass-0 compute, V1 under softmax).
// ---------------------------------------------------------------------------

#define NV 8000
#define NP 125
#define PD 22
#define PR (PD * PD * PD)
// smem float offsets (attn):
#define SM_VST 0                    // float4[108][17] = 7344 floats
#define SM_SC  7344                 // [8][128]  = 1024
#define SM_QT  8368                 // [64][8]   = 512
#define SM_WT  8880                 // [341][8] = 2728 ; also phase-1 scratch
#define SM_LG  11608                // int lutg[216]
#define SM_LP  11824                // int lutp[216]
#define SMF    12040                // 48160 B -> 4 CTAs/SM

#define FMA4(A, s, V) \
    A.x = fmaf(s, V.x, A.x); A.y = fmaf(s, V.y, A.y); \
    A.z = fmaf(s, V.z, A.z); A.w = fmaf(s, V.w, A.w)

// prefetch helpers: 108*16 = 1728 float4 slots, 256 threads -> up to 7 each
#define PF_LOAD(st, SRC, roff) \
    _Pragma("unroll") \
    for (int j = 0; j < 7; j++) { \
        int i = tid + j * 256; \
        if (i < 1728) st[j] = SRC[lutg[(roff) + (i >> 4)] + (i & 15)]; \
    }
#define PF_STORE(st) \
    _Pragma("unroll") \
    for (int j = 0; j < 7; j++) { \
        int i = tid + j * 256; \
        if (i < 1728) vst4[(i >> 4) * 17 + (i & 15)] = st[j]; \
    }

__device__ float g_Q[NV * 64];
__device__ float g_K[PR * 64];      // zero-padded
__device__ float g_V[PR * 64];      // V' (pre-Wo), zero-padded
__device__ float g_W2[64 * 64];
__device__ float g_krelT[64 * NP];
__device__ float g_vrel2[NP * 64];  // (relpos@Wv_rel + bv) @ Wo

// ---------------------------------------------------------------------------
// K1: rel tables + vrel2 (blocks 0..124) ; W2 (blocks 125..140)
// ---------------------------------------------------------------------------
__global__ void __launch_bounds__(256) rel_w2_kernel(
    const float* __restrict__ rw,
    const float* __restrict__ Wk, const float* __restrict__ bk,
    const float* __restrict__ Wv, const float* __restrict__ bv,
    const float* __restrict__ Wo)
{
    int blk = blockIdx.x;
    int tid = threadIdx.x;
    if (blk >= NP) {                       // W2: 16 blocks x 256 outputs
        int idx = (blk - NP) * 256 + tid;
        int i = idx >> 6, ch = idx & 63;
        float acc = 0.0f;
        #pragma unroll 16
        for (int k = 0; k < 64; k++)
            acc = fmaf(Wv[(96 + i) * 64 + k], Wo[k * 64 + ch], acc);
        g_W2[idx] = acc;
        return;
    }
    __shared__ float pk[3][64], pv[3][64], vsm[64], v2p[2][64];
    int p = blk;
    int ch = tid & 63;
    int part = tid >> 6;
    int a = p / 25, b = (p / 5) % 5, c = p % 5;

    if (part < 3) {
        int digit = (part == 0) ? a : (part == 1) ? b : c;
        const float* rwd = rw + digit * 32;
        const float* Wkp = Wk + part * 32 * 64 + ch;
        const float* Wvp = Wv + part * 32 * 64 + ch;
        float kk = 0.0f, vv = 0.0f;
        #pragma unroll 8
        for (int j = 0; j < 32; j++) {
            float rv = rwd[j];
            kk = fmaf(rv, Wkp[j * 64], kk);
            vv = fmaf(rv, Wvp[j * 64], vv);
        }
        pk[part][ch] = kk;
        pv[part][ch] = vv;
    }
    __syncthreads();
    if (part == 0) {
        g_krelT[ch * NP + p] = bk[ch] + (pk[0][ch] + pk[1][ch]) + pk[2][ch];
        vsm[ch]              = bv[ch] + (pv[0][ch] + pv[1][ch]) + pv[2][ch];
    }
    __syncthreads();
    if (part < 2) {
        const float* Wop = Wo + part * 32 * 64 + ch;
        const float* vp  = vsm + part * 32;
        float acc = 0.0f;
        #pragma unroll 8
        for (int k = 0; k < 32; k++)
            acc = fmaf(vp[k], Wop[k * 64], acc);
        v2p[part][ch] = acc;
    }
    __syncthreads();
    if (part == 0)
        g_vrel2[p * 64 + ch] = v2p[0][ch] + v2p[1][ch];
}

// ---------------------------------------------------------------------------
// K2: prep blocked GEMM. sel 0: Q=SE@Wq+bq ; 1: K=SE@Wk[96:] ; 2: V'=SE@W2
// ---------------------------------------------------------------------------
__global__ void __launch_bounds__(256) prep_kernel(
    const float* __restrict__ se,
    const float* __restrict__ Wq, const float* __restrict__ bq,
    const float* __restrict__ Wk)
{
    __shared__ float Wsm[64 * 64];
    __shared__ float ssm[32 * 64];
    int sel = blockIdx.y;
    int tid = threadIdx.x;
    const float* W = (sel == 0) ? Wq : (sel == 1) ? (Wk + 96 * 64) : g_W2;

    #pragma unroll
    for (int i = tid; i < 1024; i += 256)
        ((float4*)Wsm)[i] = ((const float4*)W)[i];
    int base = blockIdx.x * 32;
    #pragma unroll
    for (int i = tid; i < 512; i += 256)
        ((float4*)ssm)[i] = ((const float4*)(se + base * 64))[i];
    __syncthreads();

    int c  = tid & 63;
    int r0 = (tid >> 6) * 8;
    float acc[8];
    float bias = (sel == 0) ? bq[c] : 0.0f;
    #pragma unroll
    for (int j = 0; j < 8; j++) acc[j] = bias;

    #pragma unroll 4
    for (int k = 0; k < 64; k++) {
        float wv = Wsm[k * 64 + c];
        #pragma unroll
        for (int j = 0; j < 8; j++)
            acc[j] = fmaf(ssm[(r0 + j) * 64 + k], wv, acc[j]);
    }
    #pragma unroll
    for (int j = 0; j < 8; j++) {
        int v = base + r0 + j;
        if (sel == 0) {
            g_Q[v * 64 + c] = acc[j];
        } else {
            int x = v / 400, y = (v / 20) % 20, z = v % 20;
            int pi = ((x + 2) * PD + (y + 2)) * PD + (z + 2);
            ((sel == 1) ? g_K : g_V)[pi * 64 + c] = acc[j];
        }
    }
}

// ---------------------------------------------------------------------------
// K3: attention. 2x2x2 voxels / block, 256 threads, 4 CTAs/SM.
// ---------------------------------------------------------------------------
__global__ void __launch_bounds__(256, 4) attn_kernel(
    const float* __restrict__ bo, float* __restrict__ out)
{
    extern __shared__ float sm[];
    float4* vst4 = (float4*)(sm + SM_VST);       // [108 rows][17]
    float*  sc   = sm + SM_SC;
    float*  qt   = sm + SM_QT;
    float*  wt   = sm + SM_WT;                   // phase-1 scratch, then wt
    int*    lutg = (int*)(sm + SM_LG);
    int*    lutp = (int*)(sm + SM_LP);

    int tid = threadIdx.x;
    int bz = blockIdx.x % 10, by = (blockIdx.x / 10) % 10, bx = blockIdx.x / 100;
    int X = bx * 2, Y = by * 2, Z = bz * 2;
    int prow = (X * PD + Y) * PD + Z;

    const float4* K4 = (const float4*)g_K;
    const float4* V4 = (const float4*)g_V;
    float4 st[7];

    // ---- seg0: LUT build + qt stage ----
    if (tid < 216) {
        int r = tid;
        int rx = r / 36, rem = r - rx * 36, ry = rem / 6, rz = rem - ry * 6;
        lutg[r] = (prow + (rx * PD + ry) * PD + rz) * 16;
        lutp[r] = rx | (ry << 8) | (rz << 16);
    }
    #pragma unroll
    for (int i = tid; i < 512; i += 256) {
        int v = i >> 6, k = i & 63;
        int gv = ((X + (v >> 2)) * 20 + Y + ((v >> 1) & 1)) * 20 + Z + (v & 1);
        qt[k * 8 + v] = g_Q[gv * 64 + k];
    }
    __syncthreads();

    // ---- seg1: K1 prefetch; QR under its latency; then K1 STS ----
    PF_LOAD(st, K4, 0)
    if (tid < 250) {
        int half = tid / 125;
        int p = tid - half * 125;
        float4 a = make_float4(0.f, 0.f, 0.f, 0.f);
        const float* kp = g_krelT + p;
        #pragma unroll 8
        for (int k = 0; k < 64; k++) {
            float kr = kp[k * NP];
            float4 qv = *(const float4*)(qt + k * 8 + half * 4);
            FMA4(a, kr, qv);
        }
        sc[(half * 4 + 0) * 128 + p] = a.x;
        sc[(half * 4 + 1) * 128 + p] = a.y;
        sc[(half * 4 + 2) * 128 + p] = a.z;
        sc[(half * 4 + 3) * 128 + p] = a.w;
    }
    PF_STORE(st)
    __syncthreads();

    // ---- phase 1 pass 0: K2 prefetch; rowdot on K1 (k-split 216 thr) ----
    float acc[8];
    int rl = 0;
    PF_LOAD(st, K4, 108)
    if (tid < 216) {
        int h = tid >= 108;
        rl = tid - h * 108;
        #pragma unroll
        for (int j = 0; j < 8; j++) acc[j] = 0.0f;
        int k4A = h * 8;
        #pragma unroll
        for (int k4 = k4A; k4 < k4A + 8; k4++) {
            float4 kv = vst4[rl * 17 + k4];
            const float* qb = qt + k4 * 32;
            #pragma unroll
            for (int kk = 0; kk < 4; kk++) {
                float kf = (kk == 0) ? kv.x : (kk == 1) ? kv.y
                         : (kk == 2) ? kv.z : kv.w;
                float4 qa = *(const float4*)(qb + kk * 8);
                float4 qc = *(const float4*)(qb + kk * 8 + 4);
                acc[0] = fmaf(kf, qa.x, acc[0]); acc[1] = fmaf(kf, qa.y, acc[1]);
                acc[2] = fmaf(kf, qa.z, acc[2]); acc[3] = fmaf(kf, qa.w, acc[3]);
                acc[4] = fmaf(kf, qc.x, acc[4]); acc[5] = fmaf(kf, qc.y, acc[5]);
                acc[6] = fmaf(kf, qc.z, acc[6]); acc[7] = fmaf(kf, qc.w, acc[7]);
            }
        }
        if (tid >= 108) {
            #pragma unroll
            for (int j = 0; j < 8; j++) wt[rl * 9 + j] = acc[j];
        }
    }
    __syncthreads();

    // ---- pass-0 scatter (108 thr) + K2 STS (all threads) ----
    PF_STORE(st)
    if (tid < 108) {
        int r = tid;
        #pragma unroll
        for (int j = 0; j < 8; j++) acc[j] += wt[rl * 9 + j];
        int pk = lutp[r];
        int rx = pk & 255, ry = (pk >> 8) & 255, rz = pk >> 16;
        #pragma unroll
        for (int v = 0; v < 8; v++) {
            int lx = v >> 2, ly = (v >> 1) & 1, lz = v & 1;
            int a = ry - ly, b = rx - lx, c = rz - lz;
            if (((unsigned)a < 5u) & ((unsigned)b < 5u) & ((unsigned)c < 5u)) {
                int p = (a * 5 + b) * 5 + c;
                int mx = X + lx + a - 2, my = Y + ly + b - 2, mz = Z + lz + c - 2;
                bool mv = (mx >= 1) & (mx <= 19) & (my >= 1) & (my <= 19)
                        & (mz >= 1) & (mz <= 19);
                sc[v * 128 + p] = mv ? (sc[v * 128 + p] + acc[v]) : -1e9f;
            }
        }
    }
    __syncthreads();

    // ---- phase 1 pass 1: rowdot on K2 ----
    if (tid < 216) {
        int h = tid >= 108;
        rl = tid - h * 108;
        #pragma unroll
        for (int j = 0; j < 8; j++) acc[j] = 0.0f;
        int k4A = h * 8;
        #pragma unroll
        for (int k4 = k4A; k4 < k4A + 8; k4++) {
            float4 kv = vst4[rl * 17 + k4];
            const float* qb = qt + k4 * 32;
            #pragma unroll
            for (int kk = 0; kk < 4; kk++) {
                float kf = (kk == 0) ? kv.x : (kk == 1) ? kv.y
                         : (kk == 2) ? kv.z : kv.w;
                float4 qa = *(const float4*)(qb + kk * 8);
                float4 qc = *(const float4*)(qb + kk * 8 + 4);
                acc[0] = fmaf(kf, qa.x, acc[0]); acc[1] = fmaf(kf, qa.y, acc[1]);
                acc[2] = fmaf(kf, qa.z, acc[2]); acc[3] = fmaf(kf, qa.w, acc[3]);
                acc[4] = fmaf(kf, qc.x, acc[4]); acc[5] = fmaf(kf, qc.y, acc[5]);
                acc[6] = fmaf(kf, qc.z, acc[6]); acc[7] = fmaf(kf, qc.w, acc[7]);
            }
        }
        if (tid >= 108) {
            #pragma unroll
            for (int j = 0; j < 8; j++) wt[rl * 9 + j] = acc[j];
        }
    }
    __syncthreads();

    // ---- pass-1 scatter ----
    if (tid < 108) {
        int r = 108 + tid;
        #pragma unroll
        for (int j = 0; j < 8; j++) acc[j] += wt[rl * 9 + j];
        int pk = lutp[r];
        int rx = pk & 255, ry = (pk >> 8) & 255, rz = pk >> 16;
        #pragma unroll
        for (int v = 0; v < 8; v++) {
            int lx = v >> 2, ly = (v >> 1) & 1, lz = v & 1;
            int a = ry - ly, b = rx - lx, c = rz - lz;
            if (((unsigned)a < 5u) & ((unsigned)b < 5u) & ((unsigned)c < 5u)) {
                int p = (a * 5 + b) * 5 + c;
                int mx = X + lx + a - 2, my = Y + ly + b - 2, mz = Z + lz + c - 2;
                bool mv = (mx >= 1) & (mx <= 19) & (my >= 1) & (my <= 19)
                        & (mz >= 1) & (mz <= 19);
                sc[v * 128 + p] = mv ? (sc[v * 128 + p] + acc[v]) : -1e9f;
            }
        }
    }
    __syncthreads();

    // ---- softmax (warp = voxel) + V1 prefetch under it ----
    PF_LOAD(st, V4, 0)
    {
        int w = tid >> 5, lane = tid & 31;
        float l0 = sc[w * 128 + lane];
        float l1 = sc[w * 128 + lane + 32];
        float l2 = sc[w * 128 + lane + 64];
        float l3 = (lane < 29) ? sc[w * 128 + lane + 96] : -1e30f;
        float m = fmaxf(fmaxf(l0, l1), fmaxf(l2, l3));
        #pragma unroll
        for (int o = 16; o; o >>= 1)
            m = fmaxf(m, __shfl_xor_sync(0xffffffffu, m, o));
        float e0 = __expf(l0 - m), e1 = __expf(l1 - m);
        float e2 = __expf(l2 - m), e3 = __expf(l3 - m);
        float s = (e0 + e1) + (e2 + e3);
        #pragma unroll
        for (int o = 16; o; o >>= 1)
            s += __shfl_xor_sync(0xffffffffu, s, o);
        float inv = 1.0f / s;
        sc[w * 128 + lane]      = e0 * inv;
        sc[w * 128 + lane + 32] = e1 * inv;
        sc[w * 128 + lane + 64] = e2 * inv;
        if (lane < 29) sc[w * 128 + lane + 96] = e3 * inv;
    }
    __syncthreads();

    // ---- V1 STS + wt build [341][8] ----
    PF_STORE(st)
    for (int i = tid; i < 341 * 8; i += 256) {
        int r = i >> 3, v = i & 7;
        float w;
        if (r < 216) {
            int pk = lutp[r];
            int rx = pk & 255, ry = (pk >> 8) & 255, rz = pk >> 16;
            int lx = v >> 2, ly = (v >> 1) & 1, lz = v & 1;
            int a = ry - ly, b = rx - lx, c = rz - lz;
            w = (((unsigned)a < 5u) & ((unsigned)b < 5u) & ((unsigned)c < 5u))
                ? sc[v * 128 + (a * 5 + b) * 5 + c] : 0.0f;
        } else {
            w = sc[v * 128 + (r - 216)];
        }
        wt[i] = w;
    }
    __syncthreads();

    // ---- phase 3: value GEMM, float4 register tile, 2 passes ----
    int rg = tid >> 4, c4 = tid & 15;
    float4 a[8];
    #pragma unroll
    for (int j = 0; j < 8; j++) a[j] = make_float4(0.f, 0.f, 0.f, 0.f);

    {   // pass A: region rows 0..107 (wt rows 0..107)
        int rA = (rg * 108) >> 4;
        int rE = ((rg + 1) * 108) >> 4;
        #pragma unroll 2
        for (int r = rA; r < rE; r++) {
            float4 v4 = vst4[r * 17 + c4];
            float4 w0 = *(const float4*)(wt + r * 8);
            float4 w1 = *(const float4*)(wt + r * 8 + 4);
            FMA4(a[0], w0.x, v4); FMA4(a[1], w0.y, v4);
            FMA4(a[2], w0.z, v4); FMA4(a[3], w0.w, v4);
            FMA4(a[4], w1.x, v4); FMA4(a[5], w1.y, v4);
            FMA4(a[6], w1.z, v4); FMA4(a[7], w1.w, v4);
        }
    }
    __syncthreads();
    #pragma unroll
    for (int i = tid; i < 108 * 16; i += 256)
        vst4[(i >> 4) * 17 + (i & 15)] = V4[lutg[108 + (i >> 4)] + (i & 15)];
    __syncthreads();
    {   // pass B: region rows 108..215 + vrel2 rows (wt rows 108..340)
        const float4* VR4 = (const float4*)g_vrel2;
        int rA = (rg * 233) >> 4;
        int rE = ((rg + 1) * 233) >> 4;
        #pragma unroll 2
        for (int r = rA; r < rE; r++) {
            float4 v4 = (r < 108) ? vst4[r * 17 + c4]
                                  : VR4[(r - 108) * 16 + c4];
            const float* wr = wt + (108 + r) * 8;
            float4 w0 = *(const float4*)(wr);
            float4 w1 = *(const float4*)(wr + 4);
            FMA4(a[0], w0.x, v4); FMA4(a[1], w0.y, v4);
            FMA4(a[2], w0.z, v4); FMA4(a[3], w0.w, v4);
            FMA4(a[4], w1.x, v4); FMA4(a[5], w1.y, v4);
            FMA4(a[6], w1.z, v4); FMA4(a[7], w1.w, v4);
        }
    }
    __syncthreads();                 // vst4/sc/qt dead; reuse as partials
    float4* pts4 = (float4*)sm;      // [16 rg][8 v][16 c4]
    #pragma unroll
    for (int j = 0; j < 8; j++) pts4[rg * 128 + j * 16 + c4] = a[j];
    __syncthreads();

    // ---- reduce partials + bo, STG.128 ----
    if (tid < 128) {
        int v = tid >> 4, cc4 = tid & 15;
        float4 s = pts4[v * 16 + cc4];
        #pragma unroll
        for (int r2 = 1; r2 < 16; r2++) {
            float4 t = pts4[r2 * 128 + v * 16 + cc4];
            s.x += t.x; s.y += t.y; s.z += t.z; s.w += t.w;
        }
        float4 b4 = ((const float4*)bo)[cc4];
        s.x += b4.x; s.y += b4.y; s.z += b4.z; s.w += b4.w;
        int gv = ((X + (v >> 2)) * 20 + Y + ((v >> 1) & 1)) * 20 + Z + (v & 1);
        ((float4*)out)[gv * 16 + cc4] = s;
    }
}

// ---------------------------------------------------------------------------
// Launch
// d_in: 0=spatial_embeddings 1=relpos_w 2=Wq 3=bq 4=Wk 5=bk 6=Wv 7=bv 8=Wo 9=bo
// ---------------------------------------------------------------------------
extern "C" void kernel_launch(void* const* d_in, const int* in_sizes, int n_in,
                              void* d_out, int out_size)
{
    const float* se = (const float*)d_in[0];
    const float* rw = (const float*)d_in[1];
    const float* Wq = (const float*)d_in[2];
    const float* bq = (const float*)d_in[3];
    const float* Wk = (const float*)d_in[4];
    const float* bk = (const float*)d_in[5];
    const float* Wv = (const float*)d_in[6];
    const float* bv = (const float*)d_in[7];
    const float* Wo = (const float*)d_in[8];
    const float* bo = (const float*)d_in[9];
    float* out = (float*)d_out;

    cudaFuncSetAttribute(attn_kernel, cudaFuncAttributeMaxDynamicSharedMemorySize,
                         SMF * 4);

    rel_w2_kernel<<<NP + 16, 256>>>(rw, Wk, bk, Wv, bv, Wo);
    prep_kernel<<<dim3(250, 3), 256>>>(se, Wq, bq, Wk);
    attn_kernel<<<1000, 256, SMF * 4>>>(bo, out);
}